// round 2
// baseline (speedup 1.0000x reference)
#include <cuda_runtime.h>
#include <cuda_bf16.h>
#include <cstdint>

#define Bb 64
#define Vv 64
#define Tt 256
#define Ff 64
#define NEG_SLOPE 0.01f

// ---------------------------------------------------------------------------
// Fused kernel: block = (t, b-half). 256 threads.
//  Phase 1: load A_t -> sigmoid -> sA (swizzled), gather X[:, :, t] -> sX (swizzled)
//  Phase 2: hagg[bl][v] = sum_w sA[v][w] * sX[bl][w]   (register-tiled, LDS.128)
//  Phase 3: stream 512 KB of leaky(h*W) float4 stores at the write roofline
// Swizzle (float4 granularity): idx4 = row*16 + (wq ^ (row & 15)), scalar w&3 kept.
// ---------------------------------------------------------------------------
__global__ __launch_bounds__(256) void fused_kernel(const float* __restrict__ X,
                                                    const float* __restrict__ A,
                                                    const float* __restrict__ W,
                                                    float* __restrict__ out) {
    const int t  = blockIdx.x;        // 0..255
    const int b0 = blockIdx.y << 5;   // 0 or 32

    __shared__ float sA[Vv * Vv];     // 16 KB, swizzled
    __shared__ float sX[32 * Vv];     // 8 KB,  swizzled
    __shared__ float sH[32 * Vv];     // 8 KB,  plain [bl][v]

    const int tid = threadIdx.x;

    // Per-thread W float4 (f-group = tid & 15), with leaky pre-selection:
    // leaky(h*w) = h * (h>=0 ? leaky(w) : antileaky(w))
    float4 w4 = reinterpret_cast<const float4*>(W)[tid & 15];
    float4 wp, wn;
    wp.x = (w4.x >= 0.f) ? w4.x : NEG_SLOPE * w4.x;
    wp.y = (w4.y >= 0.f) ? w4.y : NEG_SLOPE * w4.y;
    wp.z = (w4.z >= 0.f) ? w4.z : NEG_SLOPE * w4.z;
    wp.w = (w4.w >= 0.f) ? w4.w : NEG_SLOPE * w4.w;
    wn.x = (w4.x >= 0.f) ? NEG_SLOPE * w4.x : w4.x;
    wn.y = (w4.y >= 0.f) ? NEG_SLOPE * w4.y : w4.y;
    wn.z = (w4.z >= 0.f) ? NEG_SLOPE * w4.z : w4.z;
    wn.w = (w4.w >= 0.f) ? NEG_SLOPE * w4.w : w4.w;

    // ---- Phase 1a: A_t -> sigmoid -> sA (coalesced LDG, swizzled STS) ----
    const float* At = A + (size_t)t * (Vv * Vv);
#pragma unroll
    for (int k = 0; k < 16; k++) {
        int idx = tid + k * 256;
        int v = idx >> 6, w = idx & 63;
        float a = At[idx];
        float s = (v == w) ? 1.0f : (1.0f / (1.0f + __expf(-a)));
        int f4 = (w >> 2) ^ (v & 15);
        sA[v * 64 + f4 * 4 + (w & 3)] = s;
    }
    // ---- Phase 1b: X gather (stride-T; L2 sector reuse across t-blocks) ----
#pragma unroll
    for (int k = 0; k < 8; k++) {
        int idx = tid + k * 256;       // bl*64 + w
        int bl = idx >> 6, w = idx & 63;
        float x = __ldg(&X[((size_t)(b0 + bl) * Vv + w) * Tt + t]);
        int f4 = (w >> 2) ^ (bl & 15);
        sX[bl * 64 + f4 * 4 + (w & 3)] = x;
    }
    __syncthreads();

    // ---- Phase 2: GEMM. thread tile: bl = ty+16i (i<2), v = tx+16j (j<4) ----
    const int tx = tid & 15;
    const int ty = tid >> 4;           // 0..15
    float acc[2][4];
#pragma unroll
    for (int i = 0; i < 2; i++)
#pragma unroll
        for (int j = 0; j < 4; j++) acc[i][j] = 0.f;

    const float4* sX4 = reinterpret_cast<const float4*>(sX);
    const float4* sA4 = reinterpret_cast<const float4*>(sA);
#pragma unroll
    for (int wq = 0; wq < 16; wq++) {
        // bl&15 == ty for both i; v&15 == tx for all j  -> single XOR each
        int xi = wq ^ ty;
        int ai = wq ^ tx;
        float4 xv0 = sX4[ty * 16 + xi];
        float4 xv1 = sX4[(ty + 16) * 16 + xi];
        float4 a0 = sA4[tx * 16 + ai];
        float4 a1 = sA4[(tx + 16) * 16 + ai];
        float4 a2 = sA4[(tx + 32) * 16 + ai];
        float4 a3 = sA4[(tx + 48) * 16 + ai];

        acc[0][0] = fmaf(a0.x, xv0.x, fmaf(a0.y, xv0.y, fmaf(a0.z, xv0.z, fmaf(a0.w, xv0.w, acc[0][0]))));
        acc[0][1] = fmaf(a1.x, xv0.x, fmaf(a1.y, xv0.y, fmaf(a1.z, xv0.z, fmaf(a1.w, xv0.w, acc[0][1]))));
        acc[0][2] = fmaf(a2.x, xv0.x, fmaf(a2.y, xv0.y, fmaf(a2.z, xv0.z, fmaf(a2.w, xv0.w, acc[0][2]))));
        acc[0][3] = fmaf(a3.x, xv0.x, fmaf(a3.y, xv0.y, fmaf(a3.z, xv0.z, fmaf(a3.w, xv0.w, acc[0][3]))));
        acc[1][0] = fmaf(a0.x, xv1.x, fmaf(a0.y, xv1.y, fmaf(a0.z, xv1.z, fmaf(a0.w, xv1.w, acc[1][0]))));
        acc[1][1] = fmaf(a1.x, xv1.x, fmaf(a1.y, xv1.y, fmaf(a1.z, xv1.z, fmaf(a1.w, xv1.w, acc[1][1]))));
        acc[1][2] = fmaf(a2.x, xv1.x, fmaf(a2.y, xv1.y, fmaf(a2.z, xv1.z, fmaf(a2.w, xv1.w, acc[1][2]))));
        acc[1][3] = fmaf(a3.x, xv1.x, fmaf(a3.y, xv1.y, fmaf(a3.z, xv1.z, fmaf(a3.w, xv1.w, acc[1][3]))));
    }
#pragma unroll
    for (int i = 0; i < 2; i++)
#pragma unroll
        for (int j = 0; j < 4; j++)
            sH[(ty + 16 * i) * 64 + tx + 16 * j] = acc[i][j];
    __syncthreads();

    // ---- Phase 3: stream stores. out[b, t, v*64+f] ----
    float4* o = reinterpret_cast<float4*>(out) + ((size_t)b0 * Tt + t) * 1024;
    const float* sHp = sH;
    for (int bl = 0; bl < 32; bl++) {
        float4* ob = o + (size_t)bl * (Tt * 1024);
#pragma unroll
        for (int kk = 0; kk < 4; kk++) {
            int q = tid + kk * 256;                    // float4 idx in 16 KB tile
            float h = sHp[(q >> 4)];                   // v = q/16; warp-broadcast
            bool pos = (h >= 0.f);
            float4 r;
            r.x = h * (pos ? wp.x : wn.x);
            r.y = h * (pos ? wp.y : wn.y);
            r.z = h * (pos ? wp.z : wn.z);
            r.w = h * (pos ? wp.w : wn.w);
            __stcs(ob + q, r);
        }
        sHp += 64;
    }
}

extern "C" void kernel_launch(void* const* d_in, const int* in_sizes, int n_in,
                              void* d_out, int out_size) {
    const float* X = (const float*)d_in[0];   // [B, V, T]
    const float* A = (const float*)d_in[1];   // [T, V, V]
    const float* W = (const float*)d_in[2];   // [F, 1]
    float* out = (float*)d_out;               // [B, T, V*F]

    dim3 grid(Tt, 2);
    fused_kernel<<<grid, 256>>>(X, A, W, out);
}

// round 3
// speedup vs baseline: 1.1097x; 1.1097x over previous
#include <cuda_runtime.h>
#include <cuda_bf16.h>
#include <cstdint>

#define Bb 64
#define Vv 64
#define Tt 256
#define Ff 64
#define NEG_SLOPE 0.01f

// H_agg scratch, layout [t][b][v]: kernel1 writes float2-coalesced, kernel2
// reads 256B contiguous per (b,t).
__device__ float g_hagg[(size_t)Tt * Bb * Vv];   // 4 MB

// ---------------------------------------------------------------------------
// Kernel 1: block = (t-pair, b-quarter). 128 threads, 43 KB smem.
//   sAT[t][w][v]  transposed adj, v-pair XOR-swizzled by (w&31) -> LDS.64
//                 reads conflict-free, STS 2-way worst case.
//   sXT[t][w][b]  row padded to 20 floats -> LDS.128 b-quad is a full-warp
//                 broadcast (1 wavefront), STS 4-way worst case.
// Thread (bq=tid>>5, vgr=tid&31) computes acc[2t][4b][2v]: per w per warp:
// 2x(LDS.128 + LDS.64) ~6 wavefronts vs 16 FMA instr -> FMA-bound.
// ---------------------------------------------------------------------------
__global__ __launch_bounds__(128) void hagg_kernel(const float* __restrict__ X,
                                                   const float* __restrict__ A) {
    const int t0 = blockIdx.x * 2;    // 0..254
    const int b0 = blockIdx.y * 16;   // 0,16,32,48

    __shared__ float sAT[2 * 64 * 64];   // 32 KB
    __shared__ float sXT[2 * 64 * 20];   // 10 KB (padded rows)

    const int tid = threadIdx.x;

    // ---- Load A[t0..t0+1], sigmoid+diag, store transposed+swizzled ----
    const float4* A4 = reinterpret_cast<const float4*>(A);
#pragma unroll
    for (int k = 0; k < 16; k++) {
        int idx = tid + k * 128;              // 0..2047 (float4s)
        int tIdx = idx >> 10;
        int rem = idx & 1023;                 // v*16 + wq
        int v = rem >> 4, wq = rem & 15;
        float4 a = A4[(size_t)(t0 + tIdx) * 1024 + rem];
        float av[4] = {a.x, a.y, a.z, a.w};
#pragma unroll
        for (int i = 0; i < 4; i++) {
            int w = 4 * wq + i;
            float s = (v == w) ? 1.0f
                               : __fdividef(1.0f, 1.0f + __expf(-av[i]));
            sAT[tIdx * 4096 + w * 64 + 2 * ((v >> 1) ^ (w & 31)) + (v & 1)] = s;
        }
    }
    // ---- Load X[b0..b0+15][*][t0..t0+1] as float2 along t, transpose ----
    const float2* X2 = reinterpret_cast<const float2*>(X);
#pragma unroll
    for (int k = 0; k < 8; k++) {
        int idx = tid + k * 128;              // 0..1023 : b*64 + w
        int b = idx >> 6, w = idx & 63;
        float2 x = X2[((size_t)(b0 + b) * Vv + w) * (Tt / 2) + (t0 >> 1)];
        sXT[0 * 1280 + w * 20 + b] = x.x;
        sXT[1 * 1280 + w * 20 + b] = x.y;
    }
    __syncthreads();

    // ---- GEMM ----
    const int bq  = tid >> 5;     // 0..3  -> b = b0 + 4*bq + bb
    const int vgr = tid & 31;     // v-pair index -> v = 2*vgr + {0,1}

    float acc[2][4][2];
#pragma unroll
    for (int t = 0; t < 2; t++)
#pragma unroll
        for (int bb = 0; bb < 4; bb++) { acc[t][bb][0] = 0.f; acc[t][bb][1] = 0.f; }

    const float4* sXT4 = reinterpret_cast<const float4*>(sXT);
    const float2* sAT2 = reinterpret_cast<const float2*>(sAT);

#pragma unroll 8
    for (int w = 0; w < 64; w++) {
#pragma unroll
        for (int t = 0; t < 2; t++) {
            float4 xv = sXT4[t * 320 + w * 5 + bq];           // broadcast
            float2 av = sAT2[t * 2048 + w * 32 + (vgr ^ (w & 31))];
            acc[t][0][0] = fmaf(av.x, xv.x, acc[t][0][0]);
            acc[t][0][1] = fmaf(av.y, xv.x, acc[t][0][1]);
            acc[t][1][0] = fmaf(av.x, xv.y, acc[t][1][0]);
            acc[t][1][1] = fmaf(av.y, xv.y, acc[t][1][1]);
            acc[t][2][0] = fmaf(av.x, xv.z, acc[t][2][0]);
            acc[t][2][1] = fmaf(av.y, xv.z, acc[t][2][1]);
            acc[t][3][0] = fmaf(av.x, xv.w, acc[t][3][0]);
            acc[t][3][1] = fmaf(av.y, xv.w, acc[t][3][1]);
        }
    }

    // ---- Write H_agg[t][b][v] as float2 (warp writes 256B contiguous) ----
    float2* H2 = reinterpret_cast<float2*>(g_hagg);
#pragma unroll
    for (int t = 0; t < 2; t++)
#pragma unroll
        for (int bb = 0; bb < 4; bb++) {
            int b = b0 + 4 * bq + bb;
            float2 v2; v2.x = acc[t][bb][0]; v2.y = acc[t][bb][1];
            H2[((size_t)(t0 + t) * Bb + b) * (Vv / 2) + vgr] = v2;
        }
}

// ---------------------------------------------------------------------------
// Kernel 2 (unchanged from round 1: 42.1us, 63.9% DRAM): per-(b,t) block,
// 16 KB of coalesced float4 streaming stores.
// ---------------------------------------------------------------------------
__global__ __launch_bounds__(256) void expand_kernel(const float* __restrict__ W,
                                                     float* __restrict__ out) {
    const int t = blockIdx.x;
    const int b = blockIdx.y;

    __shared__ float  sH[Vv];
    __shared__ float4 sW[Ff / 4];

    const int tid = threadIdx.x;
    if (tid < Vv) sH[tid] = g_hagg[((size_t)t * Bb + b) * Vv + tid];
    if (tid < Ff / 4) sW[tid] = reinterpret_cast<const float4*>(W)[tid];
    __syncthreads();

    float4* o = reinterpret_cast<float4*>(out) + ((size_t)b * Tt + t) * (Vv * Ff / 4);

#pragma unroll
    for (int k = 0; k < 4; k++) {
        int q = tid + k * 256;
        float h = sH[q >> 4];
        float4 w4 = sW[q & 15];
        float4 r;
        r.x = h * w4.x; r.x = (r.x >= 0.0f) ? r.x : NEG_SLOPE * r.x;
        r.y = h * w4.y; r.y = (r.y >= 0.0f) ? r.y : NEG_SLOPE * r.y;
        r.z = h * w4.z; r.z = (r.z >= 0.0f) ? r.z : NEG_SLOPE * r.z;
        r.w = h * w4.w; r.w = (r.w >= 0.0f) ? r.w : NEG_SLOPE * r.w;
        __stcs(&o[q], r);
    }
}

extern "C" void kernel_launch(void* const* d_in, const int* in_sizes, int n_in,
                              void* d_out, int out_size) {
    const float* X = (const float*)d_in[0];   // [B, V, T]
    const float* A = (const float*)d_in[1];   // [T, V, V]
    const float* W = (const float*)d_in[2];   // [F, 1]
    float* out = (float*)d_out;               // [B, T, V*F]

    dim3 grid1(Tt / 2, 4);
    hagg_kernel<<<grid1, 128>>>(X, A);
    dim3 grid2(Tt, Bb);
    expand_kernel<<<grid2, 256>>>(W, out);
}

// round 4
// speedup vs baseline: 1.3146x; 1.1847x over previous
#include <cuda_runtime.h>
#include <cuda_bf16.h>
#include <cstdint>

#define Bb 64
#define Vv 64
#define Tt 256
#define Ff 64
#define NEG_SLOPE 0.01f

// Precomputed transposed adjacency: adjT[t][w][v] = sigmoid(A[t][v][w]) off-diag, 1 on diag.
__device__ float g_adjT[(size_t)Tt * Vv * Vv];   // 4 MB

// ---------------------------------------------------------------------------
// Prep kernel: one block per t. Sigmoid computed EXACTLY ONCE per A element
// (round-3 kernel burned ~7us on 4x-redundant MUFU). Transpose via smem so
// LDG and STG are both fully coalesced.
// ---------------------------------------------------------------------------
__global__ __launch_bounds__(256) void adj_prep(const float* __restrict__ A) {
    const int t = blockIdx.x;
    __shared__ float sm[Vv][Vv + 1];   // [v][w], padded

    const int tid = threadIdx.x;
    const float4* A4 = reinterpret_cast<const float4*>(A) + (size_t)t * 1024;

#pragma unroll
    for (int k = 0; k < 4; k++) {
        int idx4 = tid + k * 256;          // v*16 + wq
        int v = idx4 >> 4, wq = idx4 & 15;
        float4 a = A4[idx4];
        float av[4] = {a.x, a.y, a.z, a.w};
#pragma unroll
        for (int i = 0; i < 4; i++) {
            int w = wq * 4 + i;
            sm[v][w] = (v == w) ? 1.0f
                                : __fdividef(1.0f, 1.0f + __expf(-av[i]));
        }
    }
    __syncthreads();

    float* dst = g_adjT + (size_t)t * 4096;
#pragma unroll
    for (int k = 0; k < 16; k++) {
        int idx = tid + k * 256;           // w*64 + v
        int w = idx >> 6, v = idx & 63;
        dst[idx] = sm[v][w];               // coalesced write, strided smem read (padded)
    }
}

// ---------------------------------------------------------------------------
// Fused GEMM + expand: block = (t, b-group of 8). Grid 2048, 256 thr, 20 KB
// smem -> 8 blocks/SM resident (1.73 waves): store parallelism matches the
// proven 41.5us expand kernel, with the tiny per-block GEMM hidden in wave
// staggering instead of serialized chip-wide in front of the store stream.
// ---------------------------------------------------------------------------
__global__ __launch_bounds__(256) void fused_kernel(const float* __restrict__ X,
                                                    const float* __restrict__ W,
                                                    float* __restrict__ out) {
    const int t  = blockIdx.x;
    const int b0 = blockIdx.y << 3;    // 0,8,...,56

    __shared__ float sAT[Vv * Vv];     // 16 KB, [w][v]
    __shared__ float sX[8][Vv];        // 2 KB
    __shared__ float sH[8][Vv];        // 2 KB

    const int tid = threadIdx.x;

    // Per-thread W quad with leaky pre-selection: leaky(h*w) = h * (h>=0 ? wp : wn)
    float4 w4 = reinterpret_cast<const float4*>(W)[tid & 15];
    float4 wp, wn;
    wp.x = (w4.x >= 0.f) ? w4.x : NEG_SLOPE * w4.x;
    wp.y = (w4.y >= 0.f) ? w4.y : NEG_SLOPE * w4.y;
    wp.z = (w4.z >= 0.f) ? w4.z : NEG_SLOPE * w4.z;
    wp.w = (w4.w >= 0.f) ? w4.w : NEG_SLOPE * w4.w;
    wn.x = (w4.x >= 0.f) ? NEG_SLOPE * w4.x : w4.x;
    wn.y = (w4.y >= 0.f) ? NEG_SLOPE * w4.y : w4.y;
    wn.z = (w4.z >= 0.f) ? NEG_SLOPE * w4.z : w4.z;
    wn.w = (w4.w >= 0.f) ? NEG_SLOPE * w4.w : w4.w;

    // Load adjT[t] (16 KB; L2-resident across the 8 b-group blocks sharing t)
    {
        const float4* src = reinterpret_cast<const float4*>(g_adjT) + (size_t)t * 1024;
        float4* dst = reinterpret_cast<float4*>(sAT);
#pragma unroll
        for (int k = 0; k < 4; k++) dst[tid + k * 256] = src[tid + k * 256];
    }
    // Gather X[b0..b0+7][*][t]
#pragma unroll
    for (int k = 0; k < 2; k++) {
        int idx = tid + k * 256;           // bb*64 + w
        int bb = idx >> 6, w = idx & 63;
        sX[bb][w] = __ldg(&X[((size_t)(b0 + bb) * Vv + w) * Tt + t]);
    }
    __syncthreads();

    // Mini-GEMM: thread (v = tid&63, g = tid>>6) computes h[g][v], h[g+4][v].
    // sAT row reads are 128B warp-contiguous (conflict-free); sX is float4 broadcast.
    {
        const int v = tid & 63;
        const int g = tid >> 6;
        const float4* x0q = reinterpret_cast<const float4*>(&sX[g][0]);
        const float4* x1q = reinterpret_cast<const float4*>(&sX[g + 4][0]);
        float a0 = 0.f, a1 = 0.f;
#pragma unroll
        for (int wq = 0; wq < 16; wq++) {
            float4 x0 = x0q[wq];
            float4 x1 = x1q[wq];
            float s0 = sAT[(4 * wq + 0) * 64 + v];
            float s1 = sAT[(4 * wq + 1) * 64 + v];
            float s2 = sAT[(4 * wq + 2) * 64 + v];
            float s3 = sAT[(4 * wq + 3) * 64 + v];
            a0 = fmaf(s0, x0.x, fmaf(s1, x0.y, fmaf(s2, x0.z, fmaf(s3, x0.w, a0))));
            a1 = fmaf(s0, x1.x, fmaf(s1, x1.y, fmaf(s2, x1.z, fmaf(s3, x1.w, a1))));
        }
        sH[g][v] = a0;
        sH[g + 4][v] = a1;
    }
    __syncthreads();

    // Store phase: 8 x 16 KB tiles of leaky(h*W), coalesced float4 streaming stores.
    float4* obase = reinterpret_cast<float4*>(out);
#pragma unroll
    for (int bb = 0; bb < 8; bb++) {
        float4* o = obase + ((size_t)(b0 + bb) * Tt + t) * 1024;
        const float* hrow = sH[bb];
#pragma unroll
        for (int k = 0; k < 4; k++) {
            int q = tid + k * 256;            // q&15 == tid&15, q>>4 = v
            float h = hrow[q >> 4];
            bool pos = (h >= 0.f);
            float4 r;
            r.x = h * (pos ? wp.x : wn.x);
            r.y = h * (pos ? wp.y : wn.y);
            r.z = h * (pos ? wp.z : wn.z);
            r.w = h * (pos ? wp.w : wn.w);
            __stcs(o + q, r);
        }
    }
}

extern "C" void kernel_launch(void* const* d_in, const int* in_sizes, int n_in,
                              void* d_out, int out_size) {
    const float* X = (const float*)d_in[0];   // [B, V, T]
    const float* A = (const float*)d_in[1];   // [T, V, V]
    const float* W = (const float*)d_in[2];   // [F, 1]
    float* out = (float*)d_out;               // [B, T, V*F]

    adj_prep<<<Tt, 256>>>(A);
    dim3 grid(Tt, Bb / 8);
    fused_kernel<<<grid, 256>>>(X, W, out);
}